// round 1
// baseline (speedup 1.0000x reference)
#include <cuda_runtime.h>
#include <cuda_bf16.h>
#include <math.h>

// Problem constants
#define B_   4
#define NO_  64
#define DO_  13
#define H_   256
#define NP_  32768

// Scratch (device globals; no allocation allowed)
__device__ float g_Anorm[B_*NO_*NO_];   // normalized adjacency
__device__ float g_mobj [B_*NO_*DO_];   // aggregated edge messages
__device__ float g_objM [B_*NO_*12];    // per-object affine map: c(3), M(9)

__device__ __forceinline__ float gelu_exact(float x) {
    return 0.5f * x * (1.0f + erff(x * 0.7071067811865476f));
}

// ---------------------------------------------------------------------------
// K0: adjacency + rigid-body precompute + dx_o cols [0:3] and [6:10]
// grid = B, block = 64 (one thread per object)
// ---------------------------------------------------------------------------
__global__ void k0_obj_prep(const float* __restrict__ xo,
                            float* __restrict__ Anorm,
                            float* __restrict__ objM,
                            float* __restrict__ dxo) {
    int b = blockIdx.x;
    int i = threadIdx.x;
    __shared__ float pos[NO_][3];

    const float* xrow = xo + (b*NO_ + i)*DO_;
    float x[13];
#pragma unroll
    for (int k = 0; k < 13; k++) x[k] = xrow[k];
    pos[i][0] = x[0]; pos[i][1] = x[1]; pos[i][2] = x[2];
    __syncthreads();

    // adjacency row (two passes, recompute exp to avoid reg-array pressure)
    const float s2 = 0.3f * 0.3f;
    float rs = 0.0f;
    for (int j = 0; j < NO_; j++) {
        float dx = x[0]-pos[j][0], dy = x[1]-pos[j][1], dz = x[2]-pos[j][2];
        float d2 = dx*dx + dy*dy + dz*dz;
        float v = (j == i) ? 1.0f : expf(-d2 / s2);
        rs += v;
    }
    for (int j = 0; j < NO_; j++) {
        float dx = x[0]-pos[j][0], dy = x[1]-pos[j][1], dz = x[2]-pos[j][2];
        float d2 = dx*dx + dy*dy + dz*dz;
        float v = (j == i) ? 1.0f : expf(-d2 / s2);
        Anorm[(b*NO_ + i)*NO_ + j] = v / rs;
    }

    // rigid body: R_eff for non-unit quaternion (exact identity for q*v*conj(q))
    float w = x[6], ux = x[7], uy = x[8], uz = x[9];
    float ox = x[10], oy = x[11], oz = x[12];
    float ss = w*w - (ux*ux + uy*uy + uz*uz);
    float R00 = ss + 2.0f*ux*ux,        R01 = 2.0f*(ux*uy - w*uz), R02 = 2.0f*(ux*uz + w*uy);
    float R10 = 2.0f*(ux*uy + w*uz),    R11 = ss + 2.0f*uy*uy,     R12 = 2.0f*(uy*uz - w*ux);
    float R20 = 2.0f*(ux*uz - w*uy),    R21 = 2.0f*(uy*uz + w*ux), R22 = ss + 2.0f*uz*uz;
    // M = skew(omega) @ R
    float M00 = -oz*R10 + oy*R20, M01 = -oz*R11 + oy*R21, M02 = -oz*R12 + oy*R22;
    float M10 =  oz*R00 - ox*R20, M11 =  oz*R01 - ox*R21, M12 =  oz*R02 - ox*R22;
    float M20 = -oy*R00 + ox*R10, M21 = -oy*R01 + ox*R11, M22 = -oy*R02 + ox*R12;
    // c = vel - M @ COM
    float c0 = x[3] - (M00*x[0] + M01*x[1] + M02*x[2]);
    float c1 = x[4] - (M10*x[0] + M11*x[1] + M12*x[2]);
    float c2 = x[5] - (M20*x[0] + M21*x[1] + M22*x[2]);

    float* om = objM + (b*NO_ + i)*12;
    om[0]=c0; om[1]=c1; om[2]=c2;
    om[3]=M00; om[4]=M01; om[5]=M02;
    om[6]=M10; om[7]=M11; om[8]=M12;
    om[9]=M20; om[10]=M21; om[11]=M22;

    // dx_o: vel and quaternion derivative
    float* orow = dxo + (b*NO_ + i)*DO_;
    orow[0] = x[3]; orow[1] = x[4]; orow[2] = x[5];
    // 0.5 * quat_mul([0,omega], q)
    float qw = x[6], qx = x[7], qy = x[8], qz = x[9];
    orow[6] = 0.5f * (-(ox*qx + oy*qy + oz*qz));
    orow[7] = 0.5f * ( ox*qw + oy*qz - oz*qy);
    orow[8] = 0.5f * (-ox*qz + oy*qw + oz*qx);
    orow[9] = 0.5f * ( ox*qy - oy*qx + oz*qw);
}

// ---------------------------------------------------------------------------
// K2: edge MLP (31->256->256->13) fused with A-weighted reduction -> m_obj
// grid = B*NO (one block per (b,i)), block = 256
// ---------------------------------------------------------------------------
#define EPAD 68   // k-major row stride (multiple of 4 for float4, minor store conflicts)

__global__ void __launch_bounds__(256, 2)
k2_edge(const float* __restrict__ xo, const float* __restrict__ tptr,
        const float* __restrict__ Anorm,
        const float* __restrict__ W0, const float* __restrict__ b0,
        const float* __restrict__ W1, const float* __restrict__ b1,
        const float* __restrict__ W2, const float* __restrict__ b2,
        float* __restrict__ mobj) {
    extern __shared__ float sm[];
    float* xo_s = sm;              // 64*13 = 832
    float* einT = sm + 832;        // 31*68 = 2108 (16B-aligned: 3328B)
    float* Arow = einT + 2108;     // 64
    float* red  = Arow + 64;       // 8*13 = 104
    float* h0T  = red + 104;       // 256*68 = 17408 (offset 3108 floats, 16B-aligned)

    int tid = threadIdx.x;
    int b = blockIdx.x >> 6, i = blockIdx.x & 63;

    const float* xb = xo + b*NO_*DO_;
    for (int idx = tid; idx < NO_*DO_; idx += 256) xo_s[idx] = xb[idx];
    for (int idx = tid; idx < NO_; idx += 256) Arow[idx] = Anorm[(b*NO_ + i)*NO_ + idx];
    __syncthreads();

    float t = *tptr;
    float xi0 = xo_s[i*13+0], xi1 = xo_s[i*13+1], xi2 = xo_s[i*13+2];
    for (int idx = tid; idx < 31*64; idx += 256) {
        int k = idx >> 6, j = idx & 63;
        float v;
        if (k < 13) v = xo_s[i*13 + k];
        else if (k < 26) v = xo_s[j*13 + (k-13)];
        else if (k < 29) v = xo_s[j*13 + (k-26)] - xo_s[i*13 + (k-26)];
        else if (k == 29) {
            float dx = xo_s[j*13+0]-xi0, dy = xo_s[j*13+1]-xi1, dz = xo_s[j*13+2]-xi2;
            v = sqrtf(dx*dx + dy*dy + dz*dz);
        } else v = t;
        einT[k*EPAD + j] = v;
    }
    __syncthreads();

    float acc[64];
    // ---- layer 0: 31 -> 256 ----
    {
        float bb = b0[tid];
#pragma unroll
        for (int j = 0; j < 64; j++) acc[j] = bb;
        for (int k = 0; k < 31; k++) {
            float w = W0[k*H_ + tid];
            const float4* er = reinterpret_cast<const float4*>(&einT[k*EPAD]);
#pragma unroll
            for (int j4 = 0; j4 < 16; j4++) {
                float4 e = er[j4];
                acc[j4*4+0] += e.x*w; acc[j4*4+1] += e.y*w;
                acc[j4*4+2] += e.z*w; acc[j4*4+3] += e.w*w;
            }
        }
#pragma unroll
        for (int j = 0; j < 64; j++) h0T[tid*EPAD + j] = gelu_exact(acc[j]);
    }
    __syncthreads();

    // ---- layer 1: 256 -> 256 ----
    {
        float bb = b1[tid];
#pragma unroll
        for (int j = 0; j < 64; j++) acc[j] = bb;
        for (int k = 0; k < 256; k++) {
            float w = W1[k*H_ + tid];
            const float4* hr = reinterpret_cast<const float4*>(&h0T[k*EPAD]);
#pragma unroll
            for (int j4 = 0; j4 < 16; j4++) {
                float4 h = hr[j4];
                acc[j4*4+0] += h.x*w; acc[j4*4+1] += h.y*w;
                acc[j4*4+2] += h.z*w; acc[j4*4+3] += h.w*w;
            }
        }
    }

    // ---- gelu + A-weighted sum over edges, then project with W2 ----
    float u = 0.0f;
#pragma unroll
    for (int j = 0; j < 64; j++) u += Arow[j] * gelu_exact(acc[j]);

    float vd[13];
#pragma unroll
    for (int d = 0; d < 13; d++) vd[d] = u * W2[tid*13 + d];
#pragma unroll
    for (int off = 16; off > 0; off >>= 1) {
#pragma unroll
        for (int d = 0; d < 13; d++) vd[d] += __shfl_down_sync(0xffffffffu, vd[d], off);
    }
    int warp = tid >> 5, lane = tid & 31;
    if (lane == 0) {
#pragma unroll
        for (int d = 0; d < 13; d++) red[warp*13 + d] = vd[d];
    }
    __syncthreads();
    if (tid < 13) {
        float s = b2[tid];
#pragma unroll
        for (int wp = 0; wp < 8; wp++) s += red[wp*13 + tid];
        mobj[(b*NO_ + i)*13 + tid] = s;
    }
}

// ---------------------------------------------------------------------------
// K3: both node MLPs (27->256->256->256->3), 8 rows per block
// grid = 64 (mlp = blk>>5; 4 batches x 8 row-chunks), block = 256
// ---------------------------------------------------------------------------
__global__ void __launch_bounds__(256)
k3_node(const float* __restrict__ xo, const float* __restrict__ mobj,
        const float* __restrict__ tptr,
        const float* __restrict__ vw0, const float* __restrict__ vb0,
        const float* __restrict__ vw1, const float* __restrict__ vb1,
        const float* __restrict__ vw2, const float* __restrict__ vb2,
        const float* __restrict__ vw3, const float* __restrict__ vb3,
        const float* __restrict__ ow0, const float* __restrict__ ob0,
        const float* __restrict__ ow1, const float* __restrict__ ob1,
        const float* __restrict__ ow2, const float* __restrict__ ob2,
        const float* __restrict__ ow3, const float* __restrict__ ob3,
        float* __restrict__ dxo) {
    __shared__ __align__(16) float inT[27*8];
    __shared__ __align__(16) float hA[256*8];
    __shared__ __align__(16) float hB[256*8];

    int tid = threadIdx.x;
    int mlp = blockIdx.x >> 5;
    int rem = blockIdx.x & 31;
    int b = rem >> 3, chunk = rem & 7;
    int i0 = chunk * 8;

    const float *W0, *B0, *W1, *B1, *W2, *B2, *W3, *B3;
    int col0;
    if (mlp == 0) { W0=vw0; B0=vb0; W1=vw1; B1=vb1; W2=vw2; B2=vb2; W3=vw3; B3=vb3; col0 = 3; }
    else          { W0=ow0; B0=ob0; W1=ow1; B1=ob1; W2=ow2; B2=ob2; W3=ow3; B3=ob3; col0 = 10; }

    float t = *tptr;
    for (int idx = tid; idx < 27*8; idx += 256) {
        int k = idx >> 3, r = idx & 7;
        int row = b*NO_ + i0 + r;
        float v;
        if (k < 13) v = xo[row*13 + k];
        else if (k < 26) v = mobj[row*13 + (k-13)];
        else v = t;
        inT[k*8 + r] = v;
    }
    __syncthreads();

    float acc[8];
    // layer 0: 27 -> 256
    {
        float bb = B0[tid];
#pragma unroll
        for (int r = 0; r < 8; r++) acc[r] = bb;
        for (int k = 0; k < 27; k++) {
            float w = W0[k*H_ + tid];
            const float4* ir = reinterpret_cast<const float4*>(&inT[k*8]);
            float4 p = ir[0], q = ir[1];
            acc[0]+=p.x*w; acc[1]+=p.y*w; acc[2]+=p.z*w; acc[3]+=p.w*w;
            acc[4]+=q.x*w; acc[5]+=q.y*w; acc[6]+=q.z*w; acc[7]+=q.w*w;
        }
#pragma unroll
        for (int r = 0; r < 8; r++) hA[tid*8 + r] = gelu_exact(acc[r]);
    }
    __syncthreads();
    // layer 1: 256 -> 256 (hA -> hB)
    {
        float bb = B1[tid];
#pragma unroll
        for (int r = 0; r < 8; r++) acc[r] = bb;
        for (int k = 0; k < 256; k++) {
            float w = W1[k*H_ + tid];
            const float4* ir = reinterpret_cast<const float4*>(&hA[k*8]);
            float4 p = ir[0], q = ir[1];
            acc[0]+=p.x*w; acc[1]+=p.y*w; acc[2]+=p.z*w; acc[3]+=p.w*w;
            acc[4]+=q.x*w; acc[5]+=q.y*w; acc[6]+=q.z*w; acc[7]+=q.w*w;
        }
#pragma unroll
        for (int r = 0; r < 8; r++) hB[tid*8 + r] = gelu_exact(acc[r]);
    }
    __syncthreads();
    // layer 2: 256 -> 256 (hB -> hA)
    {
        float bb = B2[tid];
#pragma unroll
        for (int r = 0; r < 8; r++) acc[r] = bb;
        for (int k = 0; k < 256; k++) {
            float w = W2[k*H_ + tid];
            const float4* ir = reinterpret_cast<const float4*>(&hB[k*8]);
            float4 p = ir[0], q = ir[1];
            acc[0]+=p.x*w; acc[1]+=p.y*w; acc[2]+=p.z*w; acc[3]+=p.w*w;
            acc[4]+=q.x*w; acc[5]+=q.y*w; acc[6]+=q.z*w; acc[7]+=q.w*w;
        }
#pragma unroll
        for (int r = 0; r < 8; r++) hA[tid*8 + r] = gelu_exact(acc[r]);
    }
    __syncthreads();
    // layer 3: 256 -> 3, warp w handles local row w
    {
        int wp = tid >> 5, lane = tid & 31;
        float p0 = 0.0f, p1 = 0.0f, p2 = 0.0f;
        for (int k = lane; k < 256; k += 32) {
            float h = hA[k*8 + wp];
            p0 += h * W3[k*3 + 0];
            p1 += h * W3[k*3 + 1];
            p2 += h * W3[k*3 + 2];
        }
#pragma unroll
        for (int off = 16; off > 0; off >>= 1) {
            p0 += __shfl_down_sync(0xffffffffu, p0, off);
            p1 += __shfl_down_sync(0xffffffffu, p1, off);
            p2 += __shfl_down_sync(0xffffffffu, p2, off);
        }
        if (lane == 0) {
            int row = b*NO_ + i0 + wp;
            dxo[row*13 + col0 + 0] = p0 + B3[0];
            dxo[row*13 + col0 + 1] = p1 + B3[1];
            dxo[row*13 + col0 + 2] = p2 + B3[2];
        }
    }
}

// ---------------------------------------------------------------------------
// K4: particle update.  final_vel[n] = sum_m S[n,m] * (c[m] + M[m] @ p[n])
// grid = (NP/256, B), block = 256 (one thread per particle)
// ---------------------------------------------------------------------------
#define PPB 256
#define SPAD 65  // conflict-free S tile stride

__global__ void __launch_bounds__(256)
k4_particles(const float* __restrict__ xp, const float* __restrict__ S,
             const float* __restrict__ objM, float* __restrict__ dxp) {
    extern __shared__ float sm[];
    float* Ms  = sm;            // 64*12 = 768 (16B aligned; stride 48B)
    float* Ssm = sm + 768;      // 256*65 = 16640; reused for output staging

    int tid = threadIdx.x;
    int b = blockIdx.y;
    int n0 = blockIdx.x * PPB;

    for (int idx = tid; idx < NO_*12; idx += 256) Ms[idx] = objM[b*NO_*12 + idx];
    const float* Sbase = S + ((long)b*NP_ + n0)*NO_;
    for (int idx = tid; idx < PPB*NO_; idx += 256) {
        int p = idx >> 6, m = idx & 63;
        Ssm[p*SPAD + m] = Sbase[idx];
    }
    __syncthreads();

    int n = n0 + tid;
    const float* xr = xp + ((long)b*NP_ + n)*13;
    float px = xr[10], py = xr[11], pz = xr[12];
    float cvx = xr[3], cvy = xr[4], cvz = xr[5];

    float f0 = 0.0f, f1 = 0.0f, f2 = 0.0f;
    const float* srow = &Ssm[tid*SPAD];
    const float4* Ms4 = reinterpret_cast<const float4*>(Ms);
#pragma unroll 4
    for (int m = 0; m < NO_; m++) {
        float s = srow[m];
        float4 A = Ms4[m*3+0];  // c0 c1 c2 M00
        float4 Bv = Ms4[m*3+1]; // M01 M02 M10 M11
        float4 C = Ms4[m*3+2];  // M12 M20 M21 M22
        float t0 = A.x + A.w*px + Bv.x*py + Bv.y*pz;
        float t1 = A.y + Bv.z*px + Bv.w*py + C.x*pz;
        float t2 = A.z + C.y*px + C.z*py + C.w*pz;
        f0 += s*t0; f1 += s*t1; f2 += s*t2;
    }
    __syncthreads();  // done reading Ssm; reuse it for output staging

    float* orow = &Ssm[tid*13];
    orow[0] = f0; orow[1] = f1; orow[2] = f2;
    orow[3] = f0 - cvx; orow[4] = f1 - cvy; orow[5] = f2 - cvz;
#pragma unroll
    for (int d = 6; d < 13; d++) orow[d] = 0.0f;
    __syncthreads();

    float* og = dxp + ((long)b*NP_ + n0)*13;
    for (int idx = tid; idx < PPB*13; idx += 256) og[idx] = Ssm[idx];
}

// ---------------------------------------------------------------------------
extern "C" void kernel_launch(void* const* d_in, const int* in_sizes, int n_in,
                              void* d_out, int out_size) {
    const float* t   = (const float*)d_in[0];
    const float* x_p = (const float*)d_in[1];
    const float* x_o = (const float*)d_in[2];
    const float* S   = (const float*)d_in[3];
    const float* ew0 = (const float*)d_in[4];  const float* eb0 = (const float*)d_in[5];
    const float* ew1 = (const float*)d_in[6];  const float* eb1 = (const float*)d_in[7];
    const float* ew2 = (const float*)d_in[8];  const float* eb2 = (const float*)d_in[9];
    const float* vw0 = (const float*)d_in[10]; const float* vb0 = (const float*)d_in[11];
    const float* vw1 = (const float*)d_in[12]; const float* vb1 = (const float*)d_in[13];
    const float* vw2 = (const float*)d_in[14]; const float* vb2 = (const float*)d_in[15];
    const float* vw3 = (const float*)d_in[16]; const float* vb3 = (const float*)d_in[17];
    const float* ow0 = (const float*)d_in[18]; const float* ob0 = (const float*)d_in[19];
    const float* ow1 = (const float*)d_in[20]; const float* ob1 = (const float*)d_in[21];
    const float* ow2 = (const float*)d_in[22]; const float* ob2 = (const float*)d_in[23];
    const float* ow3 = (const float*)d_in[24]; const float* ob3 = (const float*)d_in[25];

    float* out = (float*)d_out;
    float* dxp = out;                       // B*NP*13
    float* dxo = out + (long)B_*NP_*13;     // B*NO*13

    float* Anorm; cudaGetSymbolAddress((void**)&Anorm, g_Anorm);
    float* mobj;  cudaGetSymbolAddress((void**)&mobj,  g_mobj);
    float* objM;  cudaGetSymbolAddress((void**)&objM,  g_objM);

    k0_obj_prep<<<B_, NO_>>>(x_o, Anorm, objM, dxo);

    size_t sm2 = (832 + 2108 + 64 + 104 + 256*EPAD) * sizeof(float);
    cudaFuncSetAttribute(k2_edge, cudaFuncAttributeMaxDynamicSharedMemorySize, (int)sm2);
    k2_edge<<<B_*NO_, 256, sm2>>>(x_o, t, Anorm, ew0, eb0, ew1, eb1, ew2, eb2, mobj);

    k3_node<<<64, 256>>>(x_o, mobj, t,
                         vw0, vb0, vw1, vb1, vw2, vb2, vw3, vb3,
                         ow0, ob0, ow1, ob1, ow2, ob2, ow3, ob3,
                         dxo);

    size_t sm4 = (768 + PPB*SPAD) * sizeof(float);
    cudaFuncSetAttribute(k4_particles, cudaFuncAttributeMaxDynamicSharedMemorySize, (int)sm4);
    k4_particles<<<dim3(NP_/PPB, B_), 256, sm4>>>(x_p, S, objM, dxp);
}

// round 2
// speedup vs baseline: 1.0897x; 1.0897x over previous
#include <cuda_runtime.h>
#include <cuda_bf16.h>
#include <math.h>

// Problem constants
#define B_   4
#define NO_  64
#define DO_  13
#define H_   256
#define NP_  32768

// Scratch (device globals; no allocation allowed)
__device__ float g_Anorm[B_*NO_*NO_];   // normalized adjacency
__device__ float g_mobj [B_*NO_*DO_];   // aggregated edge messages
__device__ float g_objM [B_*NO_*12];    // per-object affine map: c(3), M(9)

__device__ __forceinline__ float gelu_exact(float x) {
    return 0.5f * x * (1.0f + erff(x * 0.7071067811865476f));
}

// ---- packed f32x2 helpers (FFMA2: 2 fp32 FMAs per issue, bit-exact) ----
__device__ __forceinline__ void ffma2(unsigned long long& a,
                                      unsigned long long x,
                                      unsigned long long w) {
    asm("fma.rn.f32x2 %0, %1, %2, %0;" : "+l"(a) : "l"(x), "l"(w));
}
__device__ __forceinline__ unsigned long long pack2(float lo, float hi) {
    unsigned long long r;
    asm("mov.b64 %0, {%1, %2};" : "=l"(r) : "f"(lo), "f"(hi));
    return r;
}
__device__ __forceinline__ void unpack2(unsigned long long v, float& lo, float& hi) {
    asm("mov.b64 {%0, %1}, %2;" : "=f"(lo), "=f"(hi) : "l"(v));
}

// ---------------------------------------------------------------------------
// K0: adjacency + rigid-body precompute + dx_o cols [0:3] and [6:10]
// grid = B, block = 64
// ---------------------------------------------------------------------------
__global__ void k0_obj_prep(const float* __restrict__ xo,
                            float* __restrict__ Anorm,
                            float* __restrict__ objM,
                            float* __restrict__ dxo) {
    int b = blockIdx.x;
    int i = threadIdx.x;
    __shared__ float pos[NO_][3];

    const float* xrow = xo + (b*NO_ + i)*DO_;
    float x[13];
#pragma unroll
    for (int k = 0; k < 13; k++) x[k] = xrow[k];
    pos[i][0] = x[0]; pos[i][1] = x[1]; pos[i][2] = x[2];
    __syncthreads();

    const float s2 = 0.3f * 0.3f;
    float rs = 0.0f;
    for (int j = 0; j < NO_; j++) {
        float dx = x[0]-pos[j][0], dy = x[1]-pos[j][1], dz = x[2]-pos[j][2];
        float d2 = dx*dx + dy*dy + dz*dz;
        float v = (j == i) ? 1.0f : expf(-d2 / s2);
        rs += v;
    }
    for (int j = 0; j < NO_; j++) {
        float dx = x[0]-pos[j][0], dy = x[1]-pos[j][1], dz = x[2]-pos[j][2];
        float d2 = dx*dx + dy*dy + dz*dz;
        float v = (j == i) ? 1.0f : expf(-d2 / s2);
        Anorm[(b*NO_ + i)*NO_ + j] = v / rs;
    }

    float w = x[6], ux = x[7], uy = x[8], uz = x[9];
    float ox = x[10], oy = x[11], oz = x[12];
    float ss = w*w - (ux*ux + uy*uy + uz*uz);
    float R00 = ss + 2.0f*ux*ux,        R01 = 2.0f*(ux*uy - w*uz), R02 = 2.0f*(ux*uz + w*uy);
    float R10 = 2.0f*(ux*uy + w*uz),    R11 = ss + 2.0f*uy*uy,     R12 = 2.0f*(uy*uz - w*ux);
    float R20 = 2.0f*(ux*uz - w*uy),    R21 = 2.0f*(uy*uz + w*ux), R22 = ss + 2.0f*uz*uz;
    float M00 = -oz*R10 + oy*R20, M01 = -oz*R11 + oy*R21, M02 = -oz*R12 + oy*R22;
    float M10 =  oz*R00 - ox*R20, M11 =  oz*R01 - ox*R21, M12 =  oz*R02 - ox*R22;
    float M20 = -oy*R00 + ox*R10, M21 = -oy*R01 + ox*R11, M22 = -oy*R02 + ox*R12;
    float c0 = x[3] - (M00*x[0] + M01*x[1] + M02*x[2]);
    float c1 = x[4] - (M10*x[0] + M11*x[1] + M12*x[2]);
    float c2 = x[5] - (M20*x[0] + M21*x[1] + M22*x[2]);

    float* om = objM + (b*NO_ + i)*12;
    om[0]=c0; om[1]=c1; om[2]=c2;
    om[3]=M00; om[4]=M01; om[5]=M02;
    om[6]=M10; om[7]=M11; om[8]=M12;
    om[9]=M20; om[10]=M21; om[11]=M22;

    float* orow = dxo + (b*NO_ + i)*DO_;
    orow[0] = x[3]; orow[1] = x[4]; orow[2] = x[5];
    float qw = x[6], qx = x[7], qy = x[8], qz = x[9];
    orow[6] = 0.5f * (-(ox*qx + oy*qy + oz*qz));
    orow[7] = 0.5f * ( ox*qw + oy*qz - oz*qy);
    orow[8] = 0.5f * (-ox*qz + oy*qw + oz*qx);
    orow[9] = 0.5f * ( ox*qy - oy*qx + oz*qw);
}

// ---------------------------------------------------------------------------
// K2: edge MLP (31->256->256->13) fused with A-weighted reduction -> m_obj
// grid = B*NO (one block per (b,i)), block = 256.  FFMA2 inner loops.
// ---------------------------------------------------------------------------
#define EPAD 68   // k-major row stride in floats (272B: 16B-aligned rows)

__global__ void __launch_bounds__(256, 2)
k2_edge(const float* __restrict__ xo, const float* __restrict__ tptr,
        const float* __restrict__ Anorm,
        const float* __restrict__ W0, const float* __restrict__ b0,
        const float* __restrict__ W1, const float* __restrict__ b1,
        const float* __restrict__ W2, const float* __restrict__ b2,
        float* __restrict__ mobj) {
    extern __shared__ float sm[];
    float* xo_s = sm;              // 64*13 = 832
    float* einT = sm + 832;        // 31*68 = 2108 (base byte 3328, 16B-aligned)
    float* Arow = einT + 2108;     // 64
    float* red  = Arow + 64;       // 8*13 = 104
    float* h0T  = red + 104;       // 256*68 (base byte 12432, 16B-aligned)

    int tid = threadIdx.x;
    int b = blockIdx.x >> 6, i = blockIdx.x & 63;

    const float* xb = xo + b*NO_*DO_;
    for (int idx = tid; idx < NO_*DO_; idx += 256) xo_s[idx] = xb[idx];
    for (int idx = tid; idx < NO_; idx += 256) Arow[idx] = Anorm[(b*NO_ + i)*NO_ + idx];
    __syncthreads();

    float t = *tptr;
    float xi0 = xo_s[i*13+0], xi1 = xo_s[i*13+1], xi2 = xo_s[i*13+2];
    for (int idx = tid; idx < 31*64; idx += 256) {
        int k = idx >> 6, j = idx & 63;
        float v;
        if (k < 13) v = xo_s[i*13 + k];
        else if (k < 26) v = xo_s[j*13 + (k-13)];
        else if (k < 29) v = xo_s[j*13 + (k-26)] - xo_s[i*13 + (k-26)];
        else if (k == 29) {
            float dx = xo_s[j*13+0]-xi0, dy = xo_s[j*13+1]-xi1, dz = xo_s[j*13+2]-xi2;
            v = sqrtf(dx*dx + dy*dy + dz*dz);
        } else v = t;
        einT[k*EPAD + j] = v;
    }
    __syncthreads();

    unsigned long long acc2[32];
    // ---- layer 0: 31 -> 256 ----
    {
        float bb = b0[tid];
        unsigned long long bb2 = pack2(bb, bb);
#pragma unroll
        for (int j = 0; j < 32; j++) acc2[j] = bb2;
        for (int k = 0; k < 31; k++) {
            unsigned long long w2 = pack2(W0[k*H_ + tid], W0[k*H_ + tid]);
            const ulonglong2* er = reinterpret_cast<const ulonglong2*>(&einT[k*EPAD]);
#pragma unroll
            for (int j4 = 0; j4 < 8; j4++) {
                ulonglong2 e = er[j4];
                ffma2(acc2[j4*4+0], e.x, w2);
                ffma2(acc2[j4*4+1], e.y, w2);
            }
            // second half of the row (floats 32..63)
            const ulonglong2* er2 = er + 8;
#pragma unroll
            for (int j4 = 0; j4 < 8; j4++) {
                ulonglong2 e = er2[j4];
                ffma2(acc2[j4*4+2], e.x, w2);
                ffma2(acc2[j4*4+3], e.y, w2);
            }
        }
#pragma unroll
        for (int j = 0; j < 8; j++) {
            float a, c, d, e2, f, g, h, p;
            unpack2(acc2[j*4+0], a, c);
            unpack2(acc2[j*4+1], d, e2);
            unpack2(acc2[j*4+2], f, g);
            unpack2(acc2[j*4+3], h, p);
            h0T[tid*EPAD + j*4 + 0]  = gelu_exact(a);
            h0T[tid*EPAD + j*4 + 1]  = gelu_exact(c);
            h0T[tid*EPAD + j*4 + 2]  = gelu_exact(d);
            h0T[tid*EPAD + j*4 + 3]  = gelu_exact(e2);
            h0T[tid*EPAD + 32 + j*4 + 0] = gelu_exact(f);
            h0T[tid*EPAD + 32 + j*4 + 1] = gelu_exact(g);
            h0T[tid*EPAD + 32 + j*4 + 2] = gelu_exact(h);
            h0T[tid*EPAD + 32 + j*4 + 3] = gelu_exact(p);
        }
    }
    __syncthreads();

    // ---- layer 1: 256 -> 256 ----
    {
        float bb = b1[tid];
        unsigned long long bb2 = pack2(bb, bb);
#pragma unroll
        for (int j = 0; j < 32; j++) acc2[j] = bb2;
        for (int k = 0; k < 256; k++) {
            unsigned long long w2 = pack2(W1[k*H_ + tid], W1[k*H_ + tid]);
            const ulonglong2* hr = reinterpret_cast<const ulonglong2*>(&h0T[k*EPAD]);
#pragma unroll
            for (int j4 = 0; j4 < 16; j4++) {
                ulonglong2 h = hr[j4];
                ffma2(acc2[j4*2+0], h.x, w2);
                ffma2(acc2[j4*2+1], h.y, w2);
            }
        }
    }

    // ---- gelu + A-weighted sum over edges, then project with W2 ----
    float u = 0.0f;
#pragma unroll
    for (int j2 = 0; j2 < 32; j2++) {
        float lo, hi;
        unpack2(acc2[j2], lo, hi);
        u += Arow[j2*2+0] * gelu_exact(lo);
        u += Arow[j2*2+1] * gelu_exact(hi);
    }

    float vd[13];
#pragma unroll
    for (int d = 0; d < 13; d++) vd[d] = u * W2[tid*13 + d];
#pragma unroll
    for (int off = 16; off > 0; off >>= 1) {
#pragma unroll
        for (int d = 0; d < 13; d++) vd[d] += __shfl_down_sync(0xffffffffu, vd[d], off);
    }
    int warp = tid >> 5, lane = tid & 31;
    if (lane == 0) {
#pragma unroll
        for (int d = 0; d < 13; d++) red[warp*13 + d] = vd[d];
    }
    __syncthreads();
    if (tid < 13) {
        float s = b2[tid];
#pragma unroll
        for (int wp = 0; wp < 8; wp++) s += red[wp*13 + tid];
        mobj[(b*NO_ + i)*13 + tid] = s;
    }
}

// ---------------------------------------------------------------------------
// K3: both node MLPs (27->256->256->256->3), 8 rows per block, FFMA2
// grid = 64, block = 256
// ---------------------------------------------------------------------------
__global__ void __launch_bounds__(256)
k3_node(const float* __restrict__ xo, const float* __restrict__ mobj,
        const float* __restrict__ tptr,
        const float* __restrict__ vw0, const float* __restrict__ vb0,
        const float* __restrict__ vw1, const float* __restrict__ vb1,
        const float* __restrict__ vw2, const float* __restrict__ vb2,
        const float* __restrict__ vw3, const float* __restrict__ vb3,
        const float* __restrict__ ow0, const float* __restrict__ ob0,
        const float* __restrict__ ow1, const float* __restrict__ ob1,
        const float* __restrict__ ow2, const float* __restrict__ ob2,
        const float* __restrict__ ow3, const float* __restrict__ ob3,
        float* __restrict__ dxo) {
    __shared__ __align__(16) float inT[27*8];
    __shared__ __align__(16) float hA[256*8];
    __shared__ __align__(16) float hB[256*8];

    int tid = threadIdx.x;
    int mlp = blockIdx.x >> 5;
    int rem = blockIdx.x & 31;
    int b = rem >> 3, chunk = rem & 7;
    int i0 = chunk * 8;

    const float *W0, *B0, *W1, *B1, *W2, *B2, *W3, *B3;
    int col0;
    if (mlp == 0) { W0=vw0; B0=vb0; W1=vw1; B1=vb1; W2=vw2; B2=vb2; W3=vw3; B3=vb3; col0 = 3; }
    else          { W0=ow0; B0=ob0; W1=ow1; B1=ob1; W2=ow2; B2=ob2; W3=ow3; B3=ob3; col0 = 10; }

    float t = *tptr;
    for (int idx = tid; idx < 27*8; idx += 256) {
        int k = idx >> 3, r = idx & 7;
        int row = b*NO_ + i0 + r;
        float v;
        if (k < 13) v = xo[row*13 + k];
        else if (k < 26) v = mobj[row*13 + (k-13)];
        else v = t;
        inT[k*8 + r] = v;
    }
    __syncthreads();

    unsigned long long acc2[4];
    float av[8];

#define K3_LAYER(W, BV, SRC, DST, NK)                                          \
    {                                                                          \
        float bb = BV[tid];                                                    \
        unsigned long long bb2 = pack2(bb, bb);                                \
        acc2[0]=bb2; acc2[1]=bb2; acc2[2]=bb2; acc2[3]=bb2;                    \
        for (int k = 0; k < NK; k++) {                                         \
            unsigned long long w2 = pack2(W[k*H_ + tid], W[k*H_ + tid]);       \
            const ulonglong2* ir = reinterpret_cast<const ulonglong2*>(&SRC[k*8]); \
            ulonglong2 p = ir[0], q = ir[1];                                   \
            ffma2(acc2[0], p.x, w2); ffma2(acc2[1], p.y, w2);                  \
            ffma2(acc2[2], q.x, w2); ffma2(acc2[3], q.y, w2);                  \
        }                                                                      \
        unpack2(acc2[0], av[0], av[1]); unpack2(acc2[1], av[2], av[3]);        \
        unpack2(acc2[2], av[4], av[5]); unpack2(acc2[3], av[6], av[7]);        \
        _Pragma("unroll")                                                      \
        for (int r = 0; r < 8; r++) DST[tid*8 + r] = gelu_exact(av[r]);        \
    }                                                                          \
    __syncthreads();

    K3_LAYER(W0, B0, inT, hA, 27)
    K3_LAYER(W1, B1, hA,  hB, 256)
    K3_LAYER(W2, B2, hB,  hA, 256)

    // layer 3: 256 -> 3, warp w handles local row w
    {
        int wp = tid >> 5, lane = tid & 31;
        float p0 = 0.0f, p1 = 0.0f, p2 = 0.0f;
        for (int k = lane; k < 256; k += 32) {
            float h = hA[k*8 + wp];
            p0 += h * W3[k*3 + 0];
            p1 += h * W3[k*3 + 1];
            p2 += h * W3[k*3 + 2];
        }
#pragma unroll
        for (int off = 16; off > 0; off >>= 1) {
            p0 += __shfl_down_sync(0xffffffffu, p0, off);
            p1 += __shfl_down_sync(0xffffffffu, p1, off);
            p2 += __shfl_down_sync(0xffffffffu, p2, off);
        }
        if (lane == 0) {
            int row = b*NO_ + i0 + wp;
            dxo[row*13 + col0 + 0] = p0 + B3[0];
            dxo[row*13 + col0 + 1] = p1 + B3[1];
            dxo[row*13 + col0 + 2] = p2 + B3[2];
        }
    }
}

// ---------------------------------------------------------------------------
// K4: particle update as F[n,0:12] = S[n,:] @ [c|M], then affine finalize.
// 12 independent accumulators (6 FFMA2 chains), S staged in two 32-col
// chunks (coalesced loads, ~38KB smem -> better occupancy).
// grid = (NP/256, B), block = 256
// ---------------------------------------------------------------------------
#define PPB  256
#define SPAD 36   // 32-col chunk stride (float4-phase conflict-free)

__global__ void __launch_bounds__(256)
k4_particles(const float* __restrict__ xp, const float* __restrict__ S,
             const float* __restrict__ objM, float* __restrict__ dxp) {
    extern __shared__ float sm[];
    float* Ms  = sm;            // 64*12 = 768 floats (rows 48B, 16B-aligned)
    float* Ssm = sm + 768;      // 256*36 = 9216 floats; also output staging

    int tid = threadIdx.x;
    int b = blockIdx.y;
    int n0 = blockIdx.x * PPB;

    for (int idx = tid; idx < NO_*12; idx += 256) Ms[idx] = objM[b*NO_*12 + idx];

    int n = n0 + tid;
    const float* xr = xp + ((long)b*NP_ + n)*13;
    float px = xr[10], py = xr[11], pz = xr[12];
    float cvx = xr[3], cvy = xr[4], cvz = xr[5];

    unsigned long long acc2[6];
#pragma unroll
    for (int j = 0; j < 6; j++) acc2[j] = 0ull;

    const float* Sbase = S + ((long)b*NP_ + n0)*NO_;

    for (int c = 0; c < 2; c++) {
        __syncthreads();
        // coalesced chunk load: 256 particles x 32 cols
        {
            const float4* src = reinterpret_cast<const float4*>(Sbase + c*32);
            // row p, float4-slot j (j<8): global float4 index = p*16 + j
#pragma unroll
            for (int k = 0; k < 8; k++) {
                int idx = k*256 + tid;
                int p = idx >> 3, j = idx & 7;
                float4 v = src[p*16 + j];
                *reinterpret_cast<float4*>(&Ssm[p*SPAD + j*4]) = v;
            }
        }
        __syncthreads();

        const float4* srow = reinterpret_cast<const float4*>(&Ssm[tid*SPAD]);
#pragma unroll
        for (int m4 = 0; m4 < 8; m4++) {
            float4 s4 = srow[m4];
#pragma unroll
            for (int e = 0; e < 4; e++) {
                int m = c*32 + m4*4 + e;
                float s = (e==0) ? s4.x : (e==1) ? s4.y : (e==2) ? s4.z : s4.w;
                unsigned long long s2v = pack2(s, s);
                const ulonglong2* mr = reinterpret_cast<const ulonglong2*>(Ms + m*12);
                ulonglong2 m0 = mr[0], m1 = mr[1], m2 = mr[2];
                ffma2(acc2[0], m0.x, s2v); ffma2(acc2[1], m0.y, s2v);
                ffma2(acc2[2], m1.x, s2v); ffma2(acc2[3], m1.y, s2v);
                ffma2(acc2[4], m2.x, s2v); ffma2(acc2[5], m2.y, s2v);
            }
        }
    }

    float a0,a1,a2,a3,a4,a5,a6,a7,a8,a9,a10,a11;
    unpack2(acc2[0], a0, a1);  unpack2(acc2[1], a2, a3);
    unpack2(acc2[2], a4, a5);  unpack2(acc2[3], a6, a7);
    unpack2(acc2[4], a8, a9);  unpack2(acc2[5], a10, a11);
    // layout per object row: [c0 c1 c2 M00 M01 M02 M10 M11 M12 M20 M21 M22]
    float f0 = a0 + a3*px + a4*py + a5*pz;
    float f1 = a1 + a6*px + a7*py + a8*pz;
    float f2 = a2 + a9*px + a10*py + a11*pz;

    __syncthreads();  // done reading Ssm; reuse for output staging
    float* orow = &Ssm[tid*13];
    orow[0] = f0; orow[1] = f1; orow[2] = f2;
    orow[3] = f0 - cvx; orow[4] = f1 - cvy; orow[5] = f2 - cvz;
#pragma unroll
    for (int d = 6; d < 13; d++) orow[d] = 0.0f;
    __syncthreads();

    float* og = dxp + ((long)b*NP_ + n0)*13;
    for (int idx = tid; idx < PPB*13; idx += 256) og[idx] = Ssm[idx];
}

// ---------------------------------------------------------------------------
extern "C" void kernel_launch(void* const* d_in, const int* in_sizes, int n_in,
                              void* d_out, int out_size) {
    const float* t   = (const float*)d_in[0];
    const float* x_p = (const float*)d_in[1];
    const float* x_o = (const float*)d_in[2];
    const float* S   = (const float*)d_in[3];
    const float* ew0 = (const float*)d_in[4];  const float* eb0 = (const float*)d_in[5];
    const float* ew1 = (const float*)d_in[6];  const float* eb1 = (const float*)d_in[7];
    const float* ew2 = (const float*)d_in[8];  const float* eb2 = (const float*)d_in[9];
    const float* vw0 = (const float*)d_in[10]; const float* vb0 = (const float*)d_in[11];
    const float* vw1 = (const float*)d_in[12]; const float* vb1 = (const float*)d_in[13];
    const float* vw2 = (const float*)d_in[14]; const float* vb2 = (const float*)d_in[15];
    const float* vw3 = (const float*)d_in[16]; const float* vb3 = (const float*)d_in[17];
    const float* ow0 = (const float*)d_in[18]; const float* ob0 = (const float*)d_in[19];
    const float* ow1 = (const float*)d_in[20]; const float* ob1 = (const float*)d_in[21];
    const float* ow2 = (const float*)d_in[22]; const float* ob2 = (const float*)d_in[23];
    const float* ow3 = (const float*)d_in[24]; const float* ob3 = (const float*)d_in[25];

    float* out = (float*)d_out;
    float* dxp = out;                       // B*NP*13
    float* dxo = out + (long)B_*NP_*13;     // B*NO*13

    float* Anorm; cudaGetSymbolAddress((void**)&Anorm, g_Anorm);
    float* mobj;  cudaGetSymbolAddress((void**)&mobj,  g_mobj);
    float* objM;  cudaGetSymbolAddress((void**)&objM,  g_objM);

    k0_obj_prep<<<B_, NO_>>>(x_o, Anorm, objM, dxo);

    size_t sm2 = (832 + 2108 + 64 + 104 + 256*EPAD) * sizeof(float);
    cudaFuncSetAttribute(k2_edge, cudaFuncAttributeMaxDynamicSharedMemorySize, (int)sm2);
    k2_edge<<<B_*NO_, 256, sm2>>>(x_o, t, Anorm, ew0, eb0, ew1, eb1, ew2, eb2, mobj);

    k3_node<<<64, 256>>>(x_o, mobj, t,
                         vw0, vb0, vw1, vb1, vw2, vb2, vw3, vb3,
                         ow0, ob0, ow1, ob1, ow2, ob2, ow3, ob3,
                         dxo);

    size_t sm4 = (768 + PPB*SPAD) * sizeof(float);
    cudaFuncSetAttribute(k4_particles, cudaFuncAttributeMaxDynamicSharedMemorySize, (int)sm4);
    k4_particles<<<dim3(NP_/PPB, B_), 256, sm4>>>(x_p, S, objM, dxp);
}